// round 3
// baseline (speedup 1.0000x reference)
#include <cuda_runtime.h>
#include <math_constants.h>

#define BB 256
#define DD 768
#define SPLITG 4
#define SPLITL 8

typedef unsigned long long ull;

// ---- scratch (static device globals; no allocation) ----
__device__ float d_vq[BB * DD];
__device__ float d_tlm[BB * DD];
__device__ float d_Gp[SPLITG][BB * BB];
__device__ float d_GTp[SPLITG][BB * BB];
__device__ float d_Lp[SPLITL][BB * BB];
__device__ float d_lse[3 * BB];
__device__ float d_diagG[BB];
__device__ float d_diagL[BB];

__device__ __forceinline__ float sel4(float4 v, int e) {
    return e == 0 ? v.x : e == 1 ? v.y : e == 2 ? v.z : v.w;
}
__device__ __forceinline__ ull pack2(float x, float y) {
    return (ull)__float_as_uint(x) | ((ull)__float_as_uint(y) << 32);
}
__device__ __forceinline__ float psum(ull v) {
    return __uint_as_float((unsigned)v) + __uint_as_float((unsigned)(v >> 32));
}
// packed dual-FMA: d.f32x2 = a.f32x2 * b.f32x2 + c.f32x2   (SASS: FFMA2)
__device__ __forceinline__ ull ffma2(ull a, ull b, ull c) {
    ull d;
    asm("fma.rn.f32x2 %0, %1, %2, %3;" : "=l"(d) : "l"(a), "l"(b), "l"(c));
    return d;
}

// ---- shared-memory views ----
struct K1Sm {
    ull As2[4][16 * 17];   // per warp: 16 k2 x (16 rows, pitch 17)
    ull Bs2[4][16 * 33];   // per warp: 16 k2 x (32 rows, pitch 33)
    float simb[4][512];
    float sims[512];
    float redm[16];
    float tw[16];
};
struct GemmSm {
    ull As2[16 * 66];      // 16 k2 x (64 rows, pitch 66)
    ull Bs2[16 * 66];
};
union SmU { K1Sm k1; GemmSm g; };

// ============================================================================
// GEMM body: C = A @ B^T on a 64x64 tile, K-slice [kbase, kbase+32*nch).
// 128 threads, 8x4 micro-tile (ty=tid>>4 row-group, tx=tid&15 col-group).
// Pair-major smem: As2[k2][row] = (A[row][2k2], A[row][2k2+1]).
// ============================================================================
__device__ __forceinline__ void gemm_body(GemmSm& s, const float* __restrict__ A,
                                          const float* __restrict__ Bm,
                                          float* __restrict__ C, float* __restrict__ CT,
                                          int row0, int col0, int kbase, int nch) {
    int tid = threadIdx.x;
    int ty = tid >> 4, tx = tid & 15;
    int srow = tid & 63, kh = (tid >> 6) * 16;   // staging: 2 threads/row, 16-k halves
    ull acc[8][4] = {};

    for (int ch = 0; ch < nch; ch++) {
        int kb = kbase + ch * 32;
        const float* ap = A + (size_t)(row0 + srow) * DD + kb + kh;
        const float* bp = Bm + (size_t)(col0 + srow) * DD + kb + kh;
        float4 va[4], vb[4];
#pragma unroll
        for (int q = 0; q < 4; q++) {
            va[q] = *(const float4*)(ap + 4 * q);
            vb[q] = *(const float4*)(bp + 4 * q);
        }
        __syncthreads();  // previous chunk's compute done before overwrite
#pragma unroll
        for (int q = 0; q < 4; q++) {
            int k2 = (kh >> 1) + 2 * q;
            s.As2[k2 * 66 + srow]       = pack2(va[q].x, va[q].y);
            s.As2[(k2 + 1) * 66 + srow] = pack2(va[q].z, va[q].w);
            s.Bs2[k2 * 66 + srow]       = pack2(vb[q].x, vb[q].y);
            s.Bs2[(k2 + 1) * 66 + srow] = pack2(vb[q].z, vb[q].w);
        }
        __syncthreads();
#pragma unroll
        for (int k2 = 0; k2 < 16; k2++) {
            ulonglong2 a0 = *(const ulonglong2*)&s.As2[k2 * 66 + 8 * ty];
            ulonglong2 a1 = *(const ulonglong2*)&s.As2[k2 * 66 + 8 * ty + 2];
            ulonglong2 a2 = *(const ulonglong2*)&s.As2[k2 * 66 + 8 * ty + 4];
            ulonglong2 a3 = *(const ulonglong2*)&s.As2[k2 * 66 + 8 * ty + 6];
            ulonglong2 b0 = *(const ulonglong2*)&s.Bs2[k2 * 66 + 4 * tx];
            ulonglong2 b1 = *(const ulonglong2*)&s.Bs2[k2 * 66 + 4 * tx + 2];
            ull av[8] = {a0.x, a0.y, a1.x, a1.y, a2.x, a2.y, a3.x, a3.y};
            ull bv[4] = {b0.x, b0.y, b1.x, b1.y};
#pragma unroll
            for (int i = 0; i < 8; i++)
#pragma unroll
                for (int j = 0; j < 4; j++)
                    acc[i][j] = ffma2(av[i], bv[j], acc[i][j]);
        }
    }
#pragma unroll
    for (int i = 0; i < 8; i++) {
        float4 o = make_float4(psum(acc[i][0]), psum(acc[i][1]),
                               psum(acc[i][2]), psum(acc[i][3]));
        *(float4*)&C[(size_t)(row0 + 8 * ty + i) * BB + col0 + 4 * tx] = o;
    }
    if (CT) {
#pragma unroll
        for (int j = 0; j < 4; j++) {
            float4 o0 = make_float4(psum(acc[0][j]), psum(acc[1][j]),
                                    psum(acc[2][j]), psum(acc[3][j]));
            float4 o1 = make_float4(psum(acc[4][j]), psum(acc[5][j]),
                                    psum(acc[6][j]), psum(acc[7][j]));
            float* base = &CT[(size_t)(col0 + 4 * tx + j) * BB + row0 + 8 * ty];
            *(float4*)base = o0;
            *(float4*)(base + 4) = o1;
        }
    }
}

// ============================================================================
// K1 body (per b): sim[16][32] = VL_b @ TL_b^T (K=768, 4 warps split K),
// tw = softmax_t(scale*rowmax_s), vq[b] = sum_t tw[t]*VL[b,t],
// tlm[b] = mean_s TL[b,s] folded into B staging. Pair-major smem + FFMA2.
// ============================================================================
__device__ __forceinline__ void k1_body(K1Sm& s, const float* __restrict__ VL,
                                        const float* __restrict__ TL,
                                        const float* __restrict__ temp, int b) {
    int tid = threadIdx.x, w = tid >> 5, lane = tid & 31;
    int koff = w * 192;
    int tr = lane >> 3, tc = lane & 7;

    const float* VLb = VL + (size_t)b * 16 * DD;
    const float* TLb = TL + (size_t)b * 32 * DD;

    ull* As = s.As2[w];
    ull* Bs = s.Bs2[w];
    ull acc[4][4] = {};

    for (int ks = 0; ks < 192; ks += 32) {
#pragma unroll
        for (int j = 0; j < 4; j++) {
            int idx = lane + 32 * j, row = idx >> 3, kq = idx & 7;
            float4 v = *(const float4*)(VLb + row * DD + koff + ks + 4 * kq);
            As[(2 * kq) * 17 + row]     = pack2(v.x, v.y);
            As[(2 * kq + 1) * 17 + row] = pack2(v.z, v.w);
        }
#pragma unroll
        for (int j = 0; j < 8; j++) {
            int idx = lane + 32 * j, row = idx >> 3, kq = idx & 7;
            float4 v = *(const float4*)(TLb + row * DD + koff + ks + 4 * kq);
            Bs[(2 * kq) * 33 + row]     = pack2(v.x, v.y);
            Bs[(2 * kq + 1) * 33 + row] = pack2(v.z, v.w);
        }
        __syncwarp();
#pragma unroll
        for (int k2 = 0; k2 < 16; k2++) {
            ull a0 = As[k2 * 17 + tr];
            ull a1 = As[k2 * 17 + tr + 4];
            ull a2 = As[k2 * 17 + tr + 8];
            ull a3 = As[k2 * 17 + tr + 12];
            ull b0 = Bs[k2 * 33 + tc];
            ull b1 = Bs[k2 * 33 + tc + 8];
            ull b2 = Bs[k2 * 33 + tc + 16];
            ull b3 = Bs[k2 * 33 + tc + 24];
            acc[0][0] = ffma2(a0, b0, acc[0][0]); acc[0][1] = ffma2(a0, b1, acc[0][1]);
            acc[0][2] = ffma2(a0, b2, acc[0][2]); acc[0][3] = ffma2(a0, b3, acc[0][3]);
            acc[1][0] = ffma2(a1, b0, acc[1][0]); acc[1][1] = ffma2(a1, b1, acc[1][1]);
            acc[1][2] = ffma2(a1, b2, acc[1][2]); acc[1][3] = ffma2(a1, b3, acc[1][3]);
            acc[2][0] = ffma2(a2, b0, acc[2][0]); acc[2][1] = ffma2(a2, b1, acc[2][1]);
            acc[2][2] = ffma2(a2, b2, acc[2][2]); acc[2][3] = ffma2(a2, b3, acc[2][3]);
            acc[3][0] = ffma2(a3, b0, acc[3][0]); acc[3][1] = ffma2(a3, b1, acc[3][1]);
            acc[3][2] = ffma2(a3, b2, acc[3][2]); acc[3][3] = ffma2(a3, b3, acc[3][3]);
        }
        // tlm fold: lane = k column within this 32-chunk (k2 = lane>>1, part = lane&1)
        {
            int k2 = lane >> 1, part = lane & 1;
            float tsum = 0.f;
#pragma unroll
            for (int s2 = 0; s2 < 32; s2++)
                tsum += ((const float*)&Bs[k2 * 33 + s2])[part];
            d_tlm[b * DD + koff + ks + lane] = tsum * (1.f / 32.f);
        }
        __syncwarp();
    }
#pragma unroll
    for (int i = 0; i < 4; i++)
#pragma unroll
        for (int j = 0; j < 4; j++)
            s.simb[w][(tr + 4 * i) * 32 + tc + 8 * j] = psum(acc[i][j]);
    __syncthreads();

#pragma unroll
    for (int r = 0; r < 4; r++) {
        int i = tid + 128 * r;
        s.sims[i] = s.simb[0][i] + s.simb[1][i] + s.simb[2][i] + s.simb[3][i];
    }
    __syncthreads();

    {   // row max over s
        int t = tid >> 3, g = tid & 7;
        float m = s.sims[t * 32 + g];
#pragma unroll
        for (int u = 1; u < 4; u++) m = fmaxf(m, s.sims[t * 32 + g + 8 * u]);
#pragma unroll
        for (int off = 1; off < 8; off <<= 1)
            m = fmaxf(m, __shfl_xor_sync(0xffffffffu, m, off));
        if (g == 0) s.redm[t] = m;
    }
    __syncthreads();

    if (tid < 32) {
        float scale = expf(__ldg(temp));
        float v = (lane < 16) ? s.redm[lane] * scale : -CUDART_INF_F;
        float mx = v;
#pragma unroll
        for (int o = 16; o; o >>= 1) mx = fmaxf(mx, __shfl_xor_sync(0xffffffffu, mx, o));
        float e = (lane < 16) ? expf(v - mx) : 0.f;
        float ssum = e;
#pragma unroll
        for (int o = 16; o; o >>= 1) ssum += __shfl_xor_sync(0xffffffffu, ssum, o);
        if (lane < 16) s.tw[lane] = e / ssum;
    }
    __syncthreads();

#pragma unroll
    for (int r = 0; r < 6; r++) {
        int d = tid + 128 * r;
        float a = 0.f;
#pragma unroll
        for (int t2 = 0; t2 < 16; t2++) a += s.tw[t2] * __ldg(VLb + t2 * DD + d);
        d_vq[b * DD + d] = a;
    }
}

// ============================================================================
// Fused launch 1: blocks [0,256) = k1; blocks [256,320) = G-gemm tiles.
// ============================================================================
__global__ void __launch_bounds__(128) fused_kernel(const float* __restrict__ VL,
                                                    const float* __restrict__ TL,
                                                    const float* __restrict__ VG,
                                                    const float* __restrict__ TG,
                                                    const float* __restrict__ temp) {
    __shared__ SmU sm;
    int bx = blockIdx.x;
    if (bx < 256) {
        k1_body(sm.k1, VL, TL, temp, bx);
    } else {
        int gi = bx - 256;          // 0..63
        int z = gi >> 4;            // splitK 0..3 (192 each)
        int tile = gi & 15;
        int row0 = (tile >> 2) * 64, col0 = (tile & 3) * 64;
        gemm_body(sm.g, VG, TG, d_Gp[z], d_GTp[z], row0, col0, z * 192, 6);
    }
}

// ============================================================================
// Launch 2: L = vq @ tlm^T, splitK=8 (96 each), 128 blocks.
// ============================================================================
__global__ void __launch_bounds__(128) lgemm_kernel() {
    __shared__ GemmSm sm;
    int bx = blockIdx.x;            // 0..127
    int z = bx >> 4;                // 0..7
    int tile = bx & 15;
    int row0 = (tile >> 2) * 64, col0 = (tile & 3) * 64;
    gemm_body(sm, d_vq, d_tlm, d_Lp[z], nullptr, row0, col0, z * 96, 3);
}

// ============================================================================
// Launch 3: fused partial-sum + scale + logsumexp + diag extract.
// 768 warps: [0,256) G rows; [256,512) G cols (GTp); [512,768) L rows.
// ============================================================================
__global__ void __launch_bounds__(256) lse_kernel(const float* __restrict__ temp) {
    int gw = blockIdx.x * 8 + (threadIdx.x >> 5);
    int lane = threadIdx.x & 31;
    int kind = gw >> 8, r = gw & 255;
    float scale = expf(__ldg(temp));

    float4 x0 = make_float4(0.f, 0.f, 0.f, 0.f);
    float4 x1 = make_float4(0.f, 0.f, 0.f, 0.f);
    int np = (kind == 2) ? SPLITL : SPLITG;
    for (int p = 0; p < np; p++) {
        const float* src = (kind == 0 ? d_Gp[p] : kind == 1 ? d_GTp[p] : d_Lp[p]) + r * BB;
        float4 a = ((const float4*)src)[lane];
        float4 b2 = ((const float4*)src)[lane + 32];
        x0.x += a.x; x0.y += a.y; x0.z += a.z; x0.w += a.w;
        x1.x += b2.x; x1.y += b2.y; x1.z += b2.z; x1.w += b2.w;
    }
    x0.x *= scale; x0.y *= scale; x0.z *= scale; x0.w *= scale;
    x1.x *= scale; x1.y *= scale; x1.z *= scale; x1.w *= scale;

    {   // diagonal element (col == r)
        int f = r >> 2, e = r & 3;
        if (kind == 0 && f < 32 && lane == f) d_diagG[r] = sel4(x0, e);
        if (kind == 0 && f >= 32 && lane == f - 32) d_diagG[r] = sel4(x1, e);
        if (kind == 2 && f < 32 && lane == f) d_diagL[r] = sel4(x0, e);
        if (kind == 2 && f >= 32 && lane == f - 32) d_diagL[r] = sel4(x1, e);
    }

    float m = fmaxf(fmaxf(fmaxf(x0.x, x0.y), fmaxf(x0.z, x0.w)),
                    fmaxf(fmaxf(x1.x, x1.y), fmaxf(x1.z, x1.w)));
#pragma unroll
    for (int o = 16; o; o >>= 1) m = fmaxf(m, __shfl_xor_sync(0xffffffffu, m, o));
    float ss = expf(x0.x - m) + expf(x0.y - m) + expf(x0.z - m) + expf(x0.w - m)
             + expf(x1.x - m) + expf(x1.y - m) + expf(x1.z - m) + expf(x1.w - m);
#pragma unroll
    for (int o = 16; o; o >>= 1) ss += __shfl_xor_sync(0xffffffffu, ss, o);
    if (lane == 0) d_lse[gw] = m + logf(ss);
}

// ============================================================================
// Launch 4: final combine.
// ============================================================================
__global__ void __launch_bounds__(256) final_kernel(float* __restrict__ out) {
    int tid = threadIdx.x;
    float g = d_diagG[tid];
    float l = d_diagL[tid];
    float sg = (d_lse[tid] - g) + (d_lse[256 + tid] - g);
    float sl = d_lse[512 + tid] - l;

    __shared__ float s1[8], s2[8];
    int w = tid >> 5, lane = tid & 31;
#pragma unroll
    for (int o = 16; o; o >>= 1) {
        sg += __shfl_xor_sync(0xffffffffu, sg, o);
        sl += __shfl_xor_sync(0xffffffffu, sl, o);
    }
    if (lane == 0) { s1[w] = sg; s2[w] = sl; }
    __syncthreads();
    if (tid == 0) {
        float tg = 0.f, tl = 0.f;
#pragma unroll
        for (int i = 0; i < 8; i++) { tg += s1[i]; tl += s2[i]; }
        out[0] = 0.3f * (tg / 256.f) + 0.4f * (tl / 256.f);
    }
}

extern "C" void kernel_launch(void* const* d_in, const int* in_sizes, int n_in,
                              void* d_out, int out_size) {
    const float* vg   = (const float*)d_in[0];  // video_global [256,768]
    const float* tg   = (const float*)d_in[1];  // text_global  [256,768]
    const float* vl   = (const float*)d_in[2];  // video_local  [256,16,768]
    const float* tl   = (const float*)d_in[3];  // text_local   [256,32,768]
    const float* temp = (const float*)d_in[4];  // temp [1]
    float* out = (float*)d_out;

    fused_kernel<<<320, 128>>>(vl, tl, vg, tg, temp);
    lgemm_kernel<<<128, 128>>>();
    lse_kernel<<<96, 256>>>(temp);
    final_kernel<<<1, 256>>>(out);
}

// round 5
// speedup vs baseline: 1.2382x; 1.2382x over previous
#include <cuda_runtime.h>
#include <math_constants.h>

#define BB 256
#define DD 768
#define SPLITG 4
#define SPLITL 4

// ---- scratch (static device globals; no allocation) ----
__device__ float d_vq[BB * DD];
__device__ float d_tlm[BB * DD];
__device__ float d_Gp[SPLITG][BB * BB];
__device__ float d_GTp[SPLITG][BB * BB];
__device__ float d_Lp[SPLITL][BB * BB];
__device__ float d_lse[3 * BB];
__device__ float d_diagG[BB];
__device__ float d_diagL[BB];
__device__ unsigned int d_ctr = 0;

__device__ __forceinline__ float sel4(float4 v, int e) {
    return e == 0 ? v.x : e == 1 ? v.y : e == 2 ? v.z : v.w;
}

// ---- shared-memory views ----
struct K1Sm {
    float As[4][16 * 33];
    float Bs[4][32 * 33];
    float simb[4][512];
    float sims[512];
    float redm[16];
    float tw[16];
};
struct GemmSm {
    float As[32 * 33];   // A tile: 32 rows x 32 k, pitch 33
    float Bs[64 * 33];   // B tile: 64 rows x 32 k, pitch 33
};
union SmU { K1Sm k1; GemmSm g; };

// ============================================================================
// GEMM body: C += A @ B^T on a 32x64 tile, K-slice [kbase, kbase+32*nch).
// 128 threads; thread (tr=tid>>4, tc=tid&15) owns rows {tr+8i}, cols {tc+16j}
// (4x4 micro-tile). Scalar pitch-33 smem frag loads: A broadcast, B banks
// (tc+k)%32 distinct over 16 lanes -> conflict-free.
// ============================================================================
__device__ __forceinline__ void gemm_body(GemmSm& s, const float* __restrict__ A,
                                          const float* __restrict__ Bm,
                                          float* __restrict__ C, float* __restrict__ CT,
                                          int row0, int col0, int kbase, int nch) {
    int tid = threadIdx.x;
    int tr = tid >> 4, tc = tid & 15;
    float acc[4][4] = {};

    for (int ch = 0; ch < nch; ch++) {
        int kb = kbase + ch * 32;
        float4 va[2], vb[4];
#pragma unroll
        for (int j = 0; j < 2; j++) {
            int idx = tid + 128 * j, row = idx >> 3, kq = idx & 7;
            va[j] = *(const float4*)(A + (size_t)(row0 + row) * DD + kb + 4 * kq);
        }
#pragma unroll
        for (int j = 0; j < 4; j++) {
            int idx = tid + 128 * j, row = idx >> 3, kq = idx & 7;
            vb[j] = *(const float4*)(Bm + (size_t)(col0 + row) * DD + kb + 4 * kq);
        }
        __syncthreads();  // previous chunk's compute done before overwrite
#pragma unroll
        for (int j = 0; j < 2; j++) {
            int idx = tid + 128 * j, row = idx >> 3, kq = idx & 7;
            float* p = &s.As[row * 33 + 4 * kq];
            p[0] = va[j].x; p[1] = va[j].y; p[2] = va[j].z; p[3] = va[j].w;
        }
#pragma unroll
        for (int j = 0; j < 4; j++) {
            int idx = tid + 128 * j, row = idx >> 3, kq = idx & 7;
            float* p = &s.Bs[row * 33 + 4 * kq];
            p[0] = vb[j].x; p[1] = vb[j].y; p[2] = vb[j].z; p[3] = vb[j].w;
        }
        __syncthreads();
#pragma unroll 16
        for (int k = 0; k < 32; k++) {
            float a0 = s.As[(tr)*33 + k];
            float a1 = s.As[(tr + 8) * 33 + k];
            float a2 = s.As[(tr + 16) * 33 + k];
            float a3 = s.As[(tr + 24) * 33 + k];
            float b0 = s.Bs[(tc)*33 + k];
            float b1 = s.Bs[(tc + 16) * 33 + k];
            float b2 = s.Bs[(tc + 32) * 33 + k];
            float b3 = s.Bs[(tc + 48) * 33 + k];
            acc[0][0] += a0 * b0; acc[0][1] += a0 * b1; acc[0][2] += a0 * b2; acc[0][3] += a0 * b3;
            acc[1][0] += a1 * b0; acc[1][1] += a1 * b1; acc[1][2] += a1 * b2; acc[1][3] += a1 * b3;
            acc[2][0] += a2 * b0; acc[2][1] += a2 * b1; acc[2][2] += a2 * b2; acc[2][3] += a2 * b3;
            acc[3][0] += a3 * b0; acc[3][1] += a3 * b1; acc[3][2] += a3 * b2; acc[3][3] += a3 * b3;
        }
    }
#pragma unroll
    for (int i = 0; i < 4; i++)
#pragma unroll
        for (int j = 0; j < 4; j++)
            C[(size_t)(row0 + tr + 8 * i) * BB + col0 + tc + 16 * j] = acc[i][j];
    if (CT) {
#pragma unroll
        for (int i = 0; i < 4; i++)
#pragma unroll
            for (int j = 0; j < 4; j++)
                CT[(size_t)(col0 + tc + 16 * j) * BB + row0 + tr + 8 * i] = acc[i][j];
    }
}

// ============================================================================
// K1 body (per b) — identical to the proven R2 version.
// ============================================================================
__device__ __forceinline__ void k1_body(K1Sm& s, const float* __restrict__ VL,
                                        const float* __restrict__ TL,
                                        const float* __restrict__ temp, int b) {
    int tid = threadIdx.x, w = tid >> 5, lane = tid & 31;
    int koff = w * 192;
    int tr = lane >> 3, tc = lane & 7;

    const float* VLb = VL + (size_t)b * 16 * DD;
    const float* TLb = TL + (size_t)b * 32 * DD;

    float acc[4][4] = {};

    for (int ks = 0; ks < 192; ks += 32) {
#pragma unroll
        for (int j = 0; j < 4; j++) {
            int idx = lane + 32 * j, row = idx >> 3, kq = idx & 7;
            float4 v = *(const float4*)(VLb + row * DD + koff + ks + 4 * kq);
            float* p = &s.As[w][row * 33 + 4 * kq];
            p[0] = v.x; p[1] = v.y; p[2] = v.z; p[3] = v.w;
        }
#pragma unroll
        for (int j = 0; j < 8; j++) {
            int idx = lane + 32 * j, row = idx >> 3, kq = idx & 7;
            float4 v = *(const float4*)(TLb + row * DD + koff + ks + 4 * kq);
            float* p = &s.Bs[w][row * 33 + 4 * kq];
            p[0] = v.x; p[1] = v.y; p[2] = v.z; p[3] = v.w;
        }
        __syncwarp();
#pragma unroll 16
        for (int k = 0; k < 32; k++) {
            float a0 = s.As[w][(tr)*33 + k];
            float a1 = s.As[w][(tr + 4) * 33 + k];
            float a2 = s.As[w][(tr + 8) * 33 + k];
            float a3 = s.As[w][(tr + 12) * 33 + k];
            float b0 = s.Bs[w][(tc)*33 + k];
            float b1 = s.Bs[w][(tc + 8) * 33 + k];
            float b2 = s.Bs[w][(tc + 16) * 33 + k];
            float b3 = s.Bs[w][(tc + 24) * 33 + k];
            acc[0][0] += a0 * b0; acc[0][1] += a0 * b1; acc[0][2] += a0 * b2; acc[0][3] += a0 * b3;
            acc[1][0] += a1 * b0; acc[1][1] += a1 * b1; acc[1][2] += a1 * b2; acc[1][3] += a1 * b3;
            acc[2][0] += a2 * b0; acc[2][1] += a2 * b1; acc[2][2] += a2 * b2; acc[2][3] += a2 * b3;
            acc[3][0] += a3 * b0; acc[3][1] += a3 * b1; acc[3][2] += a3 * b2; acc[3][3] += a3 * b3;
        }
        // tl_mean fold: lane = k column; sum the 32 s-rows (conflict-free)
        float tsum = 0.f;
#pragma unroll
        for (int s2 = 0; s2 < 32; s2++) tsum += s.Bs[w][s2 * 33 + lane];
        d_tlm[b * DD + koff + ks + lane] = tsum * (1.f / 32.f);
        __syncwarp();
    }
#pragma unroll
    for (int i = 0; i < 4; i++)
#pragma unroll
        for (int j = 0; j < 4; j++)
            s.simb[w][(tr + 4 * i) * 32 + tc + 8 * j] = acc[i][j];
    __syncthreads();

#pragma unroll
    for (int r = 0; r < 4; r++) {
        int i = tid + 128 * r;
        s.sims[i] = s.simb[0][i] + s.simb[1][i] + s.simb[2][i] + s.simb[3][i];
    }
    __syncthreads();

    {   // row max over s
        int t = tid >> 3, g = tid & 7;
        float m = s.sims[t * 32 + g];
#pragma unroll
        for (int u = 1; u < 4; u++) m = fmaxf(m, s.sims[t * 32 + g + 8 * u]);
#pragma unroll
        for (int off = 1; off < 8; off <<= 1)
            m = fmaxf(m, __shfl_xor_sync(0xffffffffu, m, off));
        if (g == 0) s.redm[t] = m;
    }
    __syncthreads();

    if (tid < 32) {
        float scale = expf(__ldg(temp));
        float v = (lane < 16) ? s.redm[lane] * scale : -CUDART_INF_F;
        float mx = v;
#pragma unroll
        for (int o = 16; o; o >>= 1) mx = fmaxf(mx, __shfl_xor_sync(0xffffffffu, mx, o));
        float e = (lane < 16) ? expf(v - mx) : 0.f;
        float ssum = e;
#pragma unroll
        for (int o = 16; o; o >>= 1) ssum += __shfl_xor_sync(0xffffffffu, ssum, o);
        if (lane < 16) s.tw[lane] = e / ssum;
    }
    __syncthreads();

#pragma unroll
    for (int r = 0; r < 6; r++) {
        int d = tid + 128 * r;
        float a = 0.f;
#pragma unroll
        for (int t2 = 0; t2 < 16; t2++) a += s.tw[t2] * __ldg(VLb + t2 * DD + d);
        d_vq[b * DD + d] = a;
    }
}

// ============================================================================
// Launch 1: blocks [0,256) = k1; blocks [256,384) = G-gemm (32 tiles x 4 splits).
// ============================================================================
__global__ void __launch_bounds__(128) fused_kernel(const float* __restrict__ VL,
                                                    const float* __restrict__ TL,
                                                    const float* __restrict__ VG,
                                                    const float* __restrict__ TG,
                                                    const float* __restrict__ temp) {
    __shared__ SmU sm;
    int bx = blockIdx.x;
    if (bx < 256) {
        k1_body(sm.k1, VL, TL, temp, bx);
    } else {
        int gi = bx - 256;          // 0..127
        int z = gi >> 5;            // split 0..3 (K=192 each)
        int tile = gi & 31;         // 8 row-tiles x 4 col-tiles
        int row0 = (tile >> 2) * 32, col0 = (tile & 3) * 64;
        gemm_body(sm.g, VG, TG, d_Gp[z], d_GTp[z], row0, col0, z * 192, 6);
    }
}

// ============================================================================
// Launch 2: L = vq @ tlm^T, 32 tiles x 4 splits = 128 blocks.
// ============================================================================
__global__ void __launch_bounds__(128) lgemm_kernel() {
    __shared__ GemmSm sm;
    int bx = blockIdx.x;            // 0..127
    int z = bx >> 5;
    int tile = bx & 31;
    int row0 = (tile >> 2) * 32, col0 = (tile & 3) * 64;
    gemm_body(sm, d_vq, d_tlm, d_Lp[z], nullptr, row0, col0, z * 192, 6);
}

// ============================================================================
// Launch 3: partial-sum + scale + LSE + diag, then last block does the final
// combine (threadfence-reduction pattern; counter self-resets for replay).
// 768 warps: [0,256) G rows; [256,512) G cols (GTp); [512,768) L rows.
// ============================================================================
__global__ void __launch_bounds__(256) lse_kernel(const float* __restrict__ temp,
                                                  float* __restrict__ out) {
    int gw = blockIdx.x * 8 + (threadIdx.x >> 5);
    int lane = threadIdx.x & 31;
    int kind = gw >> 8, r = gw & 255;
    float scale = expf(__ldg(temp));

    float4 x0 = make_float4(0.f, 0.f, 0.f, 0.f);
    float4 x1 = make_float4(0.f, 0.f, 0.f, 0.f);
    int np = (kind == 2) ? SPLITL : SPLITG;
    for (int p = 0; p < np; p++) {
        const float* src = (kind == 0 ? d_Gp[p] : kind == 1 ? d_GTp[p] : d_Lp[p]) + r * BB;
        float4 a = ((const float4*)src)[lane];
        float4 b2 = ((const float4*)src)[lane + 32];
        x0.x += a.x; x0.y += a.y; x0.z += a.z; x0.w += a.w;
        x1.x += b2.x; x1.y += b2.y; x1.z += b2.z; x1.w += b2.w;
    }
    x0.x *= scale; x0.y *= scale; x0.z *= scale; x0.w *= scale;
    x1.x *= scale; x1.y *= scale; x1.z *= scale; x1.w *= scale;

    {   // diagonal element (col == r)
        int f = r >> 2, e = r & 3;
        if (kind == 0 && f < 32 && lane == f) d_diagG[r] = sel4(x0, e);
        if (kind == 0 && f >= 32 && lane == f - 32) d_diagG[r] = sel4(x1, e);
        if (kind == 2 && f < 32 && lane == f) d_diagL[r] = sel4(x0, e);
        if (kind == 2 && f >= 32 && lane == f - 32) d_diagL[r] = sel4(x1, e);
    }

    float m = fmaxf(fmaxf(fmaxf(x0.x, x0.y), fmaxf(x0.z, x0.w)),
                    fmaxf(fmaxf(x1.x, x1.y), fmaxf(x1.z, x1.w)));
#pragma unroll
    for (int o = 16; o; o >>= 1) m = fmaxf(m, __shfl_xor_sync(0xffffffffu, m, o));
    float ss = expf(x0.x - m) + expf(x0.y - m) + expf(x0.z - m) + expf(x0.w - m)
             + expf(x1.x - m) + expf(x1.y - m) + expf(x1.z - m) + expf(x1.w - m);
#pragma unroll
    for (int o = 16; o; o >>= 1) ss += __shfl_xor_sync(0xffffffffu, ss, o);
    if (lane == 0) d_lse[gw] = m + logf(ss);

    // ---- last-block final combine ----
    __threadfence();
    __shared__ bool isLast;
    if (threadIdx.x == 0) {
        unsigned int old = atomicAdd(&d_ctr, 1u);
        isLast = (old == gridDim.x - 1);
    }
    __syncthreads();
    if (isLast) {
        int tid = threadIdx.x;
        float g = d_diagG[tid];
        float l = d_diagL[tid];
        float sg = (d_lse[tid] - g) + (d_lse[256 + tid] - g);
        float sl = d_lse[512 + tid] - l;

        __shared__ float s1[8], s2[8];
        int w2 = tid >> 5, l2 = tid & 31;
#pragma unroll
        for (int o = 16; o; o >>= 1) {
            sg += __shfl_xor_sync(0xffffffffu, sg, o);
            sl += __shfl_xor_sync(0xffffffffu, sl, o);
        }
        if (l2 == 0) { s1[w2] = sg; s2[w2] = sl; }
        __syncthreads();
        if (tid == 0) {
            float tg = 0.f, tl2 = 0.f;
#pragma unroll
            for (int i = 0; i < 8; i++) { tg += s1[i]; tl2 += s2[i]; }
            out[0] = 0.3f * (tg / 256.f) + 0.4f * (tl2 / 256.f);
            d_ctr = 0;  // reset for next graph replay
        }
    }
}

extern "C" void kernel_launch(void* const* d_in, const int* in_sizes, int n_in,
                              void* d_out, int out_size) {
    const float* vg   = (const float*)d_in[0];  // video_global [256,768]
    const float* tg   = (const float*)d_in[1];  // text_global  [256,768]
    const float* vl   = (const float*)d_in[2];  // video_local  [256,16,768]
    const float* tl   = (const float*)d_in[3];  // text_local   [256,32,768]
    const float* temp = (const float*)d_in[4];  // temp [1]
    float* out = (float*)d_out;

    fused_kernel<<<384, 128>>>(vl, tl, vg, tg, temp);
    lgemm_kernel<<<128, 128>>>();
    lse_kernel<<<96, 256>>>(temp, out);
}